// round 5
// baseline (speedup 1.0000x reference)
#include <cuda_runtime.h>
#include <cstdint>

#define HH 56
#define WW 56
#define HM 50
#define WM 50
#define NPLANES 16384            // 64 * 256
#define COUNT_M 51380224ull      // 64*256*56*56

// Scratch (allocation-free). Zero-initialized at module load; pass1's last CTA
// resets them every run so graph replays stay deterministic.
__device__ unsigned long long g_ones = 0ull;
__device__ unsigned g_done = 0u;
__device__ float g_scale;
__device__ unsigned long long g_dmask[NPLANES * HH];   // 7.34 MB packed dilated mask

// One CTA (128 thr) per plane. Warp w handles rows w, w+4, ... : 32 lanes load the
// row coalesced, ballots build the 50-bit seed mask, lane 0 shift-dilates
// horizontally (OR of shifts 0..6 == window [o-6, o], matching pad=6 reduce_window).
__global__ __launch_bounds__(128) void k_pass1(const float* __restrict__ u,
                                               const float* __restrict__ gamma) {
    __shared__ unsigned long long hrow[HM];
    __shared__ unsigned wsum[2];
    const int plane = blockIdx.x;
    const int tid  = threadIdx.x;
    const int wid  = tid >> 5;
    const int lane = tid & 31;
    const float g = __ldg(gamma);
    const float* base = u + (size_t)plane * (HM * WM);

    for (int r = wid; r < HM; r += 4) {
        const float* row = base + r * WM;
        unsigned lo = __ballot_sync(0xffffffffu, __ldg(row + lane) < g);
        bool b2 = false;
        if (lane < WM - 32) b2 = __ldg(row + 32 + lane) < g;   // predicated: no OOB
        unsigned hi = __ballot_sync(0xffffffffu, b2);
        if (lane == 0) {
            unsigned long long m  = ((unsigned long long)hi << 32) | lo;
            unsigned long long t1 = m  | (m  << 1);
            unsigned long long t2 = t1 | (t1 << 2);
            hrow[r] = t2 | (t2 << 3);                           // shifts 0..6
        }
    }
    __syncthreads();

    // Vertical dilation: output row o = OR of hrow[max(0,o-6) .. min(o,49)]
    unsigned v = 0;
    if (tid < HH) {
        int lo = tid - 6; if (lo < 0) lo = 0;
        int hi = (tid < HM) ? tid : (HM - 1);
        unsigned long long d = 0ull;
        #pragma unroll 1
        for (int r = lo; r <= hi; ++r) d |= hrow[r];
        g_dmask[(size_t)plane * HH + tid] = d;
        v = (unsigned)__popcll(d);
    }
    if (wid < 2) {
        #pragma unroll
        for (int off = 16; off; off >>= 1) v += __shfl_down_sync(0xffffffffu, v, off);
        if (lane == 0) wsum[wid] = v;
    }
    __syncthreads();

    if (tid == 0) {
        atomicAdd(&g_ones, (unsigned long long)(wsum[0] + wsum[1]));
        __threadfence();
        unsigned old = atomicAdd(&g_done, 1u);
        if (old == NPLANES - 1) {                // last CTA: finalize + reset
            unsigned long long ones = atomicAdd(&g_ones, 0ull);
            g_scale = (float)((double)COUNT_M / (double)(COUNT_M - ones));
            atomicExch(&g_ones, 0ull);
            atomicExch(&g_done, 0u);
        }
    }
}

// Elementwise apply, 2x float4 per thread (block covers 512 consecutive float4).
__global__ __launch_bounds__(256) void k_pass2(const float* __restrict__ x,
                                               float* __restrict__ out) {
    const unsigned i40 = blockIdx.x * 512u + threadIdx.x;
    const unsigned i41 = i40 + 256u;
    const float s = g_scale;

    const unsigned p0 = i40 / 784u, r0q = i40 - p0 * 784u;
    const unsigned row0 = r0q / 14u, w40 = r0q - row0 * 14u;
    const unsigned p1 = i41 / 784u, r1q = i41 - p1 * 784u;
    const unsigned row1 = r1q / 14u, w41 = r1q - row1 * 14u;

    const unsigned long long d0 = __ldg(&g_dmask[p0 * HH + row0]);
    const unsigned long long d1 = __ldg(&g_dmask[p1 * HH + row1]);
    const float4 x0 = __ldg(((const float4*)x) + i40);
    const float4 x1 = __ldg(((const float4*)x) + i41);

    const unsigned n0 = (unsigned)(d0 >> (w40 * 4u)) & 0xFu;
    const unsigned n1 = (unsigned)(d1 >> (w41 * 4u)) & 0xFu;
    float4 o0, o1;
    o0.x = (n0 & 1u) ? 0.f : x0.x * s;
    o0.y = (n0 & 2u) ? 0.f : x0.y * s;
    o0.z = (n0 & 4u) ? 0.f : x0.z * s;
    o0.w = (n0 & 8u) ? 0.f : x0.w * s;
    o1.x = (n1 & 1u) ? 0.f : x1.x * s;
    o1.y = (n1 & 2u) ? 0.f : x1.y * s;
    o1.z = (n1 & 4u) ? 0.f : x1.z * s;
    o1.w = (n1 & 8u) ? 0.f : x1.w * s;
    ((float4*)out)[i40] = o0;
    ((float4*)out)[i41] = o1;
}

extern "C" void kernel_launch(void* const* d_in, const int* in_sizes, int n_in,
                              void* d_out, int out_size) {
    const float* x     = (const float*)d_in[0];
    const float* u     = (const float*)d_in[1];
    const float* gamma = (const float*)d_in[2];
    float* out = (float*)d_out;

    k_pass1<<<NPLANES, 128>>>(u, gamma);
    k_pass2<<<(unsigned)(COUNT_M / 4ull / 512ull), 256>>>(x, out);   // 25088 blocks, exact
}

// round 10
// speedup vs baseline: 1.5028x; 1.5028x over previous
#include <cuda_runtime.h>
#include <cstdint>

#define HH 56
#define WW 56
#define HM 50
#define WM 50
#define NPLANES 16384            // 64 * 256
#define COUNT_M 51380224ull      // 64*256*56*56
#define NSLOTS 512

// Scratch (allocation-free). g_partial is zero at load; k_finalize resets it
// after reading, so every graph replay sees zeros again.
__device__ unsigned g_partial[NSLOTS];
__device__ float g_scale;
__device__ unsigned long long g_dmask[NPLANES * HH];   // 7.34 MB packed dilated mask

// One CTA (128 thr) per plane. Front-batched streaming loads (MLP=5), rare
// shared atomicOr to build 50 row bitmasks, separable 7x7 bit dilation
// (OR of shifts 0..6 == window [o-6,o], matching the pad=6 reduce_window).
__global__ __launch_bounds__(128) void k_pass1(const float* __restrict__ u,
                                               const float* __restrict__ gamma) {
    __shared__ unsigned long long row[HM];   // seed mask, then dilated in place
    __shared__ unsigned wsum[2];
    const int plane = blockIdx.x;
    const int tid = threadIdx.x;
    const float g = __ldg(gamma);

    if (tid < HM) row[tid] = 0ull;
    __syncthreads();

    // 625 float4 per plane; 5 batched loads per thread (last predicated).
    const float4* u4 = (const float4*)(u + (size_t)plane * (HM * WM));
    float4 v[5];
    const bool p4 = (tid < 625 - 512);
    #pragma unroll
    for (int k = 0; k < 4; ++k) v[k] = __ldcs(u4 + tid + k * 128);
    if (p4) v[4] = __ldcs(u4 + tid + 512);

    #pragma unroll
    for (int k = 0; k < 5; ++k) {
        if (k == 4 && !p4) break;
        const int e = (tid + k * 128) * 4;
        if (v[k].x < g) atomicOr(&row[ e      / WM], 1ull << ( e      % WM));
        if (v[k].y < g) atomicOr(&row[(e + 1) / WM], 1ull << ((e + 1) % WM));
        if (v[k].z < g) atomicOr(&row[(e + 2) / WM], 1ull << ((e + 2) % WM));
        if (v[k].w < g) atomicOr(&row[(e + 3) / WM], 1ull << ((e + 3) % WM));
    }
    __syncthreads();

    // Horizontal dilation, in place (rows independent).
    if (tid < HM) {
        unsigned long long m  = row[tid];
        unsigned long long t1 = m  | (m  << 1);
        unsigned long long t2 = t1 | (t1 << 2);
        row[tid] = t2 | (t2 << 3);                 // shifts 0..6, bits stay < 56
    }
    __syncthreads();

    // Vertical dilation: output row o = OR of row[max(0,o-6) .. min(o,49)]
    unsigned v1 = 0;
    if (tid < HH) {
        int lo = tid - 6; if (lo < 0) lo = 0;
        int hi = (tid < HM) ? tid : (HM - 1);
        unsigned long long d = 0ull;
        #pragma unroll 1
        for (int r = lo; r <= hi; ++r) d |= row[r];
        g_dmask[(size_t)plane * HH + tid] = d;
        v1 = (unsigned)__popcll(d);
    }
    if (tid < 64) {
        #pragma unroll
        for (int off = 16; off; off >>= 1) v1 += __shfl_down_sync(0xffffffffu, v1, off);
        if ((tid & 31) == 0) wsum[tid >> 5] = v1;
    }
    __syncthreads();
    if (tid == 0)
        atomicAdd(&g_partial[plane & (NSLOTS - 1)], wsum[0] + wsum[1]);  // spread slots
}

// One block: sum the 512 slots, compute scale (f32, like the jnp reference),
// reset slots for the next replay.
__global__ __launch_bounds__(NSLOTS) void k_finalize() {
    __shared__ unsigned s[NSLOTS / 32];
    const int tid = threadIdx.x;
    unsigned v = g_partial[tid];
    g_partial[tid] = 0u;
    #pragma unroll
    for (int off = 16; off; off >>= 1) v += __shfl_down_sync(0xffffffffu, v, off);
    if ((tid & 31) == 0) s[tid >> 5] = v;
    __syncthreads();
    if (tid < 32) {
        unsigned w = (tid < NSLOTS / 32) ? s[tid] : 0u;
        #pragma unroll
        for (int off = 8; off; off >>= 1) w += __shfl_down_sync(0xffffffffu, w, off);
        if (tid == 0)
            g_scale = (float)COUNT_M / (float)(COUNT_M - (unsigned long long)w);
    }
}

// Elementwise apply, 2x float4 per thread, streaming loads/stores.
__global__ __launch_bounds__(256) void k_pass2(const float* __restrict__ x,
                                               float* __restrict__ out) {
    const unsigned i40 = blockIdx.x * 512u + threadIdx.x;
    const unsigned i41 = i40 + 256u;
    const float s = g_scale;

    const unsigned p0 = i40 / 784u, r0q = i40 - p0 * 784u;
    const unsigned row0 = r0q / 14u, w40 = r0q - row0 * 14u;
    const unsigned p1 = i41 / 784u, r1q = i41 - p1 * 784u;
    const unsigned row1 = r1q / 14u, w41 = r1q - row1 * 14u;

    const unsigned long long d0 = __ldg(&g_dmask[p0 * HH + row0]);
    const unsigned long long d1 = __ldg(&g_dmask[p1 * HH + row1]);
    const float4 x0 = __ldcs(((const float4*)x) + i40);
    const float4 x1 = __ldcs(((const float4*)x) + i41);

    const unsigned n0 = (unsigned)(d0 >> (w40 * 4u)) & 0xFu;
    const unsigned n1 = (unsigned)(d1 >> (w41 * 4u)) & 0xFu;
    float4 o0, o1;
    o0.x = (n0 & 1u) ? 0.f : x0.x * s;
    o0.y = (n0 & 2u) ? 0.f : x0.y * s;
    o0.z = (n0 & 4u) ? 0.f : x0.z * s;
    o0.w = (n0 & 8u) ? 0.f : x0.w * s;
    o1.x = (n1 & 1u) ? 0.f : x1.x * s;
    o1.y = (n1 & 2u) ? 0.f : x1.y * s;
    o1.z = (n1 & 4u) ? 0.f : x1.z * s;
    o1.w = (n1 & 8u) ? 0.f : x1.w * s;
    __stcs(((float4*)out) + i40, o0);
    __stcs(((float4*)out) + i41, o1);
}

extern "C" void kernel_launch(void* const* d_in, const int* in_sizes, int n_in,
                              void* d_out, int out_size) {
    const float* x     = (const float*)d_in[0];
    const float* u     = (const float*)d_in[1];
    const float* gamma = (const float*)d_in[2];
    float* out = (float*)d_out;

    k_pass1<<<NPLANES, 128>>>(u, gamma);
    k_finalize<<<1, NSLOTS>>>();
    k_pass2<<<(unsigned)(COUNT_M / 4ull / 512ull), 256>>>(x, out);   // 25088 blocks
}